// round 1
// baseline (speedup 1.0000x reference)
#include <cuda_runtime.h>
#include <cstdint>
#include <math.h>

#define D_  512
#define NB_ 2048
#define TT_ 64
#define MT_ (NB_*TT_)   // 131072 rows for the time-parallel projection GEMM

// ---------------- scratch (device globals: no allocation allowed) ----------------
__device__ __align__(16) float g_xproj[(size_t)MT_ * 1536]; // [b*T+t, (z|r|h) pre-proj]
__device__ __align__(16) float g_W1[1536 * D_];             // concat(Wzx, Wrx, Whx), row-major [n,k]
__device__ __align__(16) float g_Wg[1024 * D_];             // concat(Wzh, Wrh)
__device__ __align__(16) float g_bias[1536];                // concat(bz, br, bh)
__device__ __align__(16) float g_h[NB_ * D_];               // hidden state
__device__ __align__(16) float g_z[NB_ * D_];               // z gate
__device__ __align__(16) float g_u[NB_ * D_];               // r * h

// ---------------- helpers ----------------
__device__ __forceinline__ unsigned f2t(float x) {
    unsigned r;
    asm("cvt.rna.tf32.f32 %0, %1;" : "=r"(r) : "f"(x));
    return r;
}

__device__ __forceinline__ void mma8(float* d, const unsigned* a, const unsigned* b) {
    asm volatile(
        "mma.sync.aligned.m16n8k8.row.col.f32.tf32.tf32.f32 "
        "{%0,%1,%2,%3},{%4,%5,%6,%7},{%8,%9},{%0,%1,%2,%3};"
        : "+f"(d[0]), "+f"(d[1]), "+f"(d[2]), "+f"(d[3])
        : "r"(a[0]), "r"(a[1]), "r"(a[2]), "r"(a[3]), "r"(b[0]), "r"(b[1]));
}

__device__ __forceinline__ float sigmoidf_(float x) {
    return 1.0f / (1.0f + expf(-x));
}

// ---------------- prep: pack weights/biases, zero h ----------------
__global__ void prep_kernel(const float* __restrict__ Wzx, const float* __restrict__ Wzh,
                            const float* __restrict__ Wrx, const float* __restrict__ Wrh,
                            const float* __restrict__ Whx,
                            const float* __restrict__ bz, const float* __restrict__ br,
                            const float* __restrict__ bh) {
    int i = blockIdx.x * blockDim.x + threadIdx.x;
    const int WN = D_ * D_;
    if (i < WN) {
        g_W1[i]          = Wzx[i];
        g_W1[WN + i]     = Wrx[i];
        g_W1[2 * WN + i] = Whx[i];
        g_Wg[i]          = Wzh[i];
        g_Wg[WN + i]     = Wrh[i];
    }
    if (i < 1536) g_bias[i] = (i < 512) ? bz[i] : (i < 1024 ? br[i - 512] : bh[i - 1024]);
    if (i < NB_ * D_) g_h[i] = 0.0f;
}

// ---------------- fused tf32x3 GEMM ----------------
// C[M,N] = A[M,K=512] * B[N,K=512]^T, M,N multiples of 128.
// MODE 0: A = X (arg), B = g_W1,  epilogue: += bias, store to g_xproj          (grid 12 x 1024)
// MODE 1: A = g_h,    B = g_Wg,  epilogue: z = sigm(.+xz) -> g_z; u = sigm(.+xr)*h -> g_u  (grid 8 x 16)
// MODE 2: A = g_u,    B = Whh,   epilogue: ht = tanh(.+xh); h = z*h+(1-z)*ht -> g_h, out   (grid 4 x 16)
template <int MODE>
__global__ __launch_bounds__(256, 1) void gemm_k(const float* __restrict__ A_arg,
                                                 const float* __restrict__ B_arg,
                                                 float* __restrict__ out, int t) {
    extern __shared__ float sm[];
    const int STRIDE = 128 * 36;          // padded row stride 36 -> conflict-free frag loads
    float* As = sm;                       // [2][128*36]
    float* Bs = sm + 2 * STRIDE;          // [2][128*36]

    const float* __restrict__ A = (MODE == 0) ? A_arg : (MODE == 1 ? g_h : g_u);
    const float* __restrict__ B = (MODE == 0) ? g_W1 : (MODE == 1 ? g_Wg : B_arg);

    const int tid  = threadIdx.x;
    const int lane = tid & 31, warp = tid >> 5;
    const int wm = warp >> 2, wn = warp & 3;   // 2 x 4 warp grid, warptile 64x32
    const int g  = lane >> 2, tg = lane & 3;
    const int bm = blockIdx.y * 128, bn = blockIdx.x * 128;

    const int lrow = tid >> 3;            // 0..31 (4 rows per thread, stride 32)
    const int lcol = (tid & 7) << 2;      // 0,4,...,28

    const float* Ag = A + (size_t)(bm + lrow) * D_ + lcol;
    const float* Bg = B + (size_t)(bn + lrow) * D_ + lcol;

    float acc[4][4][4];
#pragma unroll
    for (int i = 0; i < 4; i++)
#pragma unroll
        for (int j = 0; j < 4; j++)
#pragma unroll
            for (int e = 0; e < 4; e++) acc[i][j][e] = 0.0f;

    float4 ra[4], rb[4];
#pragma unroll
    for (int i = 0; i < 4; i++) {
        ra[i] = *(const float4*)(Ag + (size_t)i * 32 * D_);
        rb[i] = *(const float4*)(Bg + (size_t)i * 32 * D_);
    }
#pragma unroll
    for (int i = 0; i < 4; i++) {
        *(float4*)(&As[(lrow + i * 32) * 36 + lcol]) = ra[i];
        *(float4*)(&Bs[(lrow + i * 32) * 36 + lcol]) = rb[i];
    }
    __syncthreads();

    int buf = 0;
#pragma unroll 1
    for (int kt = 0; kt < 16; kt++) {
        if (kt < 15) {
            const float* Ag2 = Ag + (kt + 1) * 32;
            const float* Bg2 = Bg + (kt + 1) * 32;
#pragma unroll
            for (int i = 0; i < 4; i++) {
                ra[i] = *(const float4*)(Ag2 + (size_t)i * 32 * D_);
                rb[i] = *(const float4*)(Bg2 + (size_t)i * 32 * D_);
            }
        }
        const float* Ab = As + buf * STRIDE;
        const float* Bb = Bs + buf * STRIDE;
#pragma unroll
        for (int kk = 0; kk < 4; kk++) {
            const int k0 = kk * 8;
            unsigned ahi[4][4], alo[4][4], bhi[4][2], blo[4][2];
#pragma unroll
            for (int i = 0; i < 4; i++) {
                const int r0 = wm * 64 + i * 16 + g;
                float a0 = Ab[r0 * 36 + k0 + tg];
                float a1 = Ab[(r0 + 8) * 36 + k0 + tg];
                float a2 = Ab[r0 * 36 + k0 + tg + 4];
                float a3 = Ab[(r0 + 8) * 36 + k0 + tg + 4];
                ahi[i][0] = f2t(a0); alo[i][0] = f2t(a0 - __uint_as_float(ahi[i][0]));
                ahi[i][1] = f2t(a1); alo[i][1] = f2t(a1 - __uint_as_float(ahi[i][1]));
                ahi[i][2] = f2t(a2); alo[i][2] = f2t(a2 - __uint_as_float(ahi[i][2]));
                ahi[i][3] = f2t(a3); alo[i][3] = f2t(a3 - __uint_as_float(ahi[i][3]));
            }
#pragma unroll
            for (int j = 0; j < 4; j++) {
                const int n0 = wn * 32 + j * 8 + g;
                float b0 = Bb[n0 * 36 + k0 + tg];
                float b1 = Bb[n0 * 36 + k0 + tg + 4];
                bhi[j][0] = f2t(b0); blo[j][0] = f2t(b0 - __uint_as_float(bhi[j][0]));
                bhi[j][1] = f2t(b1); blo[j][1] = f2t(b1 - __uint_as_float(bhi[j][1]));
            }
            // tf32x3: hi*hi, lo*hi, hi*lo (lo*lo term ~2^-22, dropped)
#pragma unroll
            for (int i = 0; i < 4; i++)
#pragma unroll
                for (int j = 0; j < 4; j++) mma8(acc[i][j], ahi[i], bhi[j]);
#pragma unroll
            for (int i = 0; i < 4; i++)
#pragma unroll
                for (int j = 0; j < 4; j++) mma8(acc[i][j], alo[i], bhi[j]);
#pragma unroll
            for (int i = 0; i < 4; i++)
#pragma unroll
                for (int j = 0; j < 4; j++) mma8(acc[i][j], ahi[i], blo[j]);
        }
        if (kt < 15) {
            float* An = As + (buf ^ 1) * STRIDE;
            float* Bn = Bs + (buf ^ 1) * STRIDE;
#pragma unroll
            for (int i = 0; i < 4; i++) {
                *(float4*)(&An[(lrow + i * 32) * 36 + lcol]) = ra[i];
                *(float4*)(&Bn[(lrow + i * 32) * 36 + lcol]) = rb[i];
            }
            __syncthreads();
        }
        buf ^= 1;
    }

    // ---------------- epilogue ----------------
#pragma unroll
    for (int i = 0; i < 4; i++) {
#pragma unroll
        for (int j = 0; j < 4; j++) {
#pragma unroll
            for (int e = 0; e < 4; e++) {
                const int row = bm + wm * 64 + i * 16 + g + ((e >> 1) << 3);
                const int col = bn + wn * 32 + j * 8 + (tg << 1) + (e & 1);
                float v = acc[i][j][e];
                if (MODE == 0) {
                    v += g_bias[col];
                    g_xproj[(size_t)row * 1536 + col] = v;
                } else if (MODE == 1) {
                    const size_t xb = ((size_t)row * TT_ + t) * 1536;
                    if (col < 512) {
                        g_z[row * D_ + col] = sigmoidf_(v + g_xproj[xb + col]);
                    } else {
                        const int c = col - 512;
                        float rr = sigmoidf_(v + g_xproj[xb + 512 + c]);
                        g_u[row * D_ + c] = rr * g_h[row * D_ + c];
                    }
                } else {
                    const size_t xb = ((size_t)row * TT_ + t) * 1536;
                    float ht = tanhf(v + g_xproj[xb + 1024 + col]);
                    float zz = g_z[row * D_ + col];
                    float ho = g_h[row * D_ + col];
                    float hn = zz * ho + (1.0f - zz) * ht;
                    g_h[row * D_ + col] = hn;
                    out[((size_t)row * TT_ + t) * D_ + col] = hn;
                }
            }
        }
    }
}

// ---------------- launch ----------------
extern "C" void kernel_launch(void* const* d_in, const int* in_sizes, int n_in,
                              void* d_out, int out_size) {
    const float* X   = (const float*)d_in[0];
    const float* Wzx = (const float*)d_in[1];
    const float* Wzh = (const float*)d_in[2];
    const float* Wrx = (const float*)d_in[3];
    const float* Wrh = (const float*)d_in[4];
    const float* Whx = (const float*)d_in[5];
    const float* Whh = (const float*)d_in[6];
    const float* bz  = (const float*)d_in[7];
    const float* br  = (const float*)d_in[8];
    const float* bh  = (const float*)d_in[9];
    float* out = (float*)d_out;

    const int SMEM = 2 * 2 * 128 * 36 * (int)sizeof(float);  // 73728 B
    cudaFuncSetAttribute(gemm_k<0>, cudaFuncAttributeMaxDynamicSharedMemorySize, SMEM);
    cudaFuncSetAttribute(gemm_k<1>, cudaFuncAttributeMaxDynamicSharedMemorySize, SMEM);
    cudaFuncSetAttribute(gemm_k<2>, cudaFuncAttributeMaxDynamicSharedMemorySize, SMEM);

    prep_kernel<<<(NB_ * D_ + 255) / 256, 256>>>(Wzx, Wzh, Wrx, Wrh, Whx, bz, br, bh);

    // Phase 1: all input projections, one big GEMM [131072 x 1536]
    gemm_k<0><<<dim3(1536 / 128, MT_ / 128), 256, SMEM>>>(X, Whh, out, 0);

    // Phase 2: sequential recurrence
    for (int t = 0; t < TT_; t++) {
        gemm_k<1><<<dim3(1024 / 128, NB_ / 128), 256, SMEM>>>(X, Whh, out, t);
        gemm_k<2><<<dim3(512 / 128, NB_ / 128), 256, SMEM>>>(X, Whh, out, t);
    }
}